// round 3
// baseline (speedup 1.0000x reference)
#include <cuda_runtime.h>
#include <cstdint>

// SpottingLoss: greedy bipartite matching (2 phases) + YOLO-style loss.
// B=2048 batches, N=64 slots, F=19 features. One CTA (64 threads) per batch.

#define N_ 64
#define F_ 19
#define LAMBDA_COORD 5.0f
#define LAMBDA_NOOBJ 0.5f

__global__ void zero_kernel(float* out, int n) {
    int i = blockIdx.x * blockDim.x + threadIdx.x;
    if (i < n) out[i] = 0.0f;
}

__global__ __launch_bounds__(N_) void spotting_loss_kernel(
    const float* __restrict__ y_true,
    const float* __restrict__ y_pred,
    float* __restrict__ out)
{
    __shared__ float yt[N_ * F_];
    __shared__ float yp[N_ * F_];
    __shared__ unsigned long long colkey[N_];
    __shared__ unsigned long long free_mask;
    __shared__ float red[2];

    const int b   = blockIdx.x;
    const int tid = threadIdx.x;

    // Stage both tiles coalesced into smem (64*19 floats each).
    const float* gt = y_true + (size_t)b * (N_ * F_);
    const float* gp = y_pred + (size_t)b * (N_ * F_);
    for (int idx = tid; idx < N_ * F_; idx += N_) {
        yt[idx] = gt[idx];
        yp[idx] = gp[idx];
    }
    colkey[tid] = 0ull;
    if (tid == 0) free_mask = ~0ull;
    __syncthreads();

    const float alpha = yt[tid * F_ + 0];   // exactly 0.0f or 1.0f
    const float x     = yt[tid * F_ + 1];
    int perm = 0;   // argmax of an all-zero Permut row is 0 (defensive default)

    // Two phases: phase 0 matches alpha==1 rows, phase 1 matches alpha==0 rows
    // against the columns left free. Comparison value is D1[i,j] = 1 - |x_i - p_j|
    // (> 0 always), restricted to free columns. Ties: argmax-first-index semantics.
    for (int phase = 0; phase < 2; ++phase) {
        bool active = (phase == 0) ? (alpha > 0.5f) : (alpha <= 0.5f);

        for (int it = 0; it < N_; ++it) {
            if (__syncthreads_count(active) == 0) break;   // barrier A (uniform)

            int bj = 0;
            if (active) {
                // Row proposal: scan free columns only (bitmask-pruned).
                unsigned long long fm = free_mask;
                float best = -1.0f;
                while (fm) {
                    int j = __ffsll((long long)fm) - 1;
                    fm &= fm - 1;
                    float v = 1.0f - fabsf(x - yp[j * F_ + 1]);
                    if (v > best) { best = v; bj = j; }   // strict > keeps lowest j on ties
                }
                // Column acceptance key: (value bits << 32) | ~row.
                // best > 0 so float bits are monotone; larger key = larger value,
                // then lower row index — exactly JAX argmax tie-breaking.
                unsigned long long key =
                    ((unsigned long long)__float_as_uint(best) << 32) |
                    (unsigned long long)(0xFFFFFFFFu - (unsigned)tid);
                atomicMax(&colkey[bj], key);
            }
            __syncthreads();                               // barrier B

            bool matched = false;
            if (active) {
                unsigned long long k = colkey[bj];
                unsigned wr = 0xFFFFFFFFu - (unsigned)(k & 0xFFFFFFFFull);
                matched = (wr == (unsigned)tid);
            }
            __syncthreads();                               // barrier C (reads done)

            if (matched) {
                active = false;
                perm   = bj;
                atomicAnd(&free_mask, ~(1ull << bj));
            }
            colkey[tid] = 0ull;   // reset for next round (visible after barrier A)
        }
    }
    __syncthreads();

    // Loss for row tid using permuted prediction yp[perm, :].
    const float* ypr = &yp[perm * F_];
    const float a  = alpha;
    const float d0 = a - ypr[0];
    const float dx = yt[tid * F_ + 1] - ypr[1];
    float s = 0.0f;
#pragma unroll
    for (int f = 2; f < F_; ++f) {
        float d = yt[tid * F_ + f] - ypr[f];
        s += d * d;
    }
    float term = a * (LAMBDA_COORD * dx * dx + d0 * d0 + s)
               + (1.0f - a) * (LAMBDA_NOOBJ * d0 * d0);

    // Block reduction (2 warps) then one atomicAdd per batch.
#pragma unroll
    for (int o = 16; o; o >>= 1) term += __shfl_down_sync(0xFFFFFFFFu, term, o);
    if ((tid & 31) == 0) red[tid >> 5] = term;
    __syncthreads();
    if (tid == 0) atomicAdd(out, red[0] + red[1]);
}

extern "C" void kernel_launch(void* const* d_in, const int* in_sizes, int n_in,
                              void* d_out, int out_size)
{
    const float* y_true = (const float*)d_in[0];
    const float* y_pred = (const float*)d_in[1];
    float* out = (float*)d_out;

    zero_kernel<<<(out_size + 255) / 256, 256>>>(out, out_size);

    int batches = in_sizes[0] / (N_ * F_);   // 2048
    spotting_loss_kernel<<<batches, N_>>>(y_true, y_pred, out);
}